// round 15
// baseline (speedup 1.0000x reference)
#include <cuda_runtime.h>
#include <cuda_fp16.h>
#include <cstdint>

// ============================================================================
// helpers
// ============================================================================
__device__ __forceinline__ uint32_t smem_u32(const void* p) {
    uint32_t a;
    asm("{ .reg .u64 t; cvta.to.shared.u64 t, %1; cvt.u32.u64 %0, t; }" : "=r"(a) : "l"(p));
    return a;
}
__host__ __device__ __forceinline__ uint32_t swz128(uint32_t off) {
    return off ^ ((off >> 3) & 0x70);
}
__device__ __forceinline__ void ldsm4(uint32_t r[4], uint32_t addr) {
    asm volatile("ldmatrix.sync.aligned.m8n8.x4.shared.b16 {%0,%1,%2,%3}, [%4];"
                 : "=r"(r[0]), "=r"(r[1]), "=r"(r[2]), "=r"(r[3]) : "r"(addr));
}
__device__ __forceinline__ void mma16816(float d[4], const uint32_t a[4], uint32_t b0, uint32_t b1) {
    asm volatile("mma.sync.aligned.m16n8k16.row.col.f32.f16.f16.f32 "
                 "{%0,%1,%2,%3}, {%4,%5,%6,%7}, {%8,%9}, {%0,%1,%2,%3};"
                 : "+f"(d[0]), "+f"(d[1]), "+f"(d[2]), "+f"(d[3])
                 : "r"(a[0]), "r"(a[1]), "r"(a[2]), "r"(a[3]), "r"(b0), "r"(b1));
}
__device__ __forceinline__ void cpa16(uint32_t dst, const void* src) {
    asm volatile("cp.async.cg.shared.global [%0], [%1], 16;" :: "r"(dst), "l"(src));
}
#define CP_COMMIT() asm volatile("cp.async.commit_group;" ::: "memory")
#define CP_WAIT0()  asm volatile("cp.async.wait_group 0;" ::: "memory")

// ============================================================================
// smem layout (per CTA 66,560 B; 3 CTAs/SM = 199,680 B)
// ============================================================================
static constexpr int SMEM_A0   = 0;        // 16 KB: A 128x64 fp16 (buf 0)
static constexpr int SMEM_A1   = 16384;    // 16 KB: A buf 1
static constexpr int SMEM_B0   = 32768;    // 12 KB: B half (96n) buf 0
static constexpr int SMEM_B1   = 45056;    // 12 KB: B half buf 1
static constexpr int OFF_PSUM  = 57344;    // 4 KB
static constexpr int OFF_PSQ   = 61440;    // 4 KB
static constexpr int OFF_STAT  = 65536;    // 1 KB
static constexpr int SMEM_TOTAL = 66560;

static constexpr int NUM_TILES = 512;      // 256 m-tiles x 2 n-halves
static constexpr int GRID      = 444;      // 148 SMs x 3 CTAs, single wave

// ---------------- device scratch ----------------
__device__ float  g_s1[192];
__device__ float  g_s2[192];
__device__ float4 g_Bh[12 * 1536];   // 12 chunks x 24KB (192n x 128B rows), pre-swizzled

// ---------------- prep kernel: B plane + s1/s2 ----------------
__global__ void k_prep(const float* __restrict__ gamma, const float* __restrict__ beta,
                       const float* __restrict__ w) {
    if (blockIdx.x < 576) {
        int t = blockIdx.x * 256 + threadIdx.x;
        int k = t / 192;       // original k = p*96 + c
        int n = t % 192;
        int p = k / 96, c = k % 96;
        float val = gamma[k] * w[k * 192 + n];
        int chunk = c >> 3;
        int kl = (c & 7) * 8 + p;              // k-hat within chunk
        uint32_t off = swz128((uint32_t)(n * 128 + kl * 2));
        *(__half*)((unsigned char*)g_Bh + chunk * 24576 + off) = __float2half_rn(val);
    } else {
        int n = blockIdx.x - 576;
        __shared__ float s1s[256], s2s[256];
        float s1 = 0.f, s2 = 0.f;
        for (int k = threadIdx.x; k < 768; k += 256) {
            float wv = w[k * 192 + n];
            s1 += gamma[k] * wv;
            s2 += beta[k] * wv;
        }
        s1s[threadIdx.x] = s1; s2s[threadIdx.x] = s2;
        __syncthreads();
        for (int off = 128; off > 0; off >>= 1) {
            if (threadIdx.x < off) { s1s[threadIdx.x] += s1s[threadIdx.x + off]; s2s[threadIdx.x] += s2s[threadIdx.x + off]; }
            __syncthreads();
        }
        if (threadIdx.x == 0) { g_s1[n] = s1s[0]; g_s2[n] = s2s[0]; }
    }
}

// ---------------- main fused kernel (persistent over tiles) ----------------
__global__ void __launch_bounds__(256, 3) k_main(const float* __restrict__ x,
                                                 float* __restrict__ out) {
    extern __shared__ unsigned char smem[];
    const uint32_t sb  = smem_u32(smem);
    const int tid  = threadIdx.x;
    const int lane = tid & 31;
    const int wrp  = tid >> 5;
    const int wm   = wrp & 3;       // M quadrant (32 rows)
    const int wn   = wrp >> 2;      // n sub-half (48 cols of CTA's 96)

    const int idx = tid >> 5;       // c_local 0..7 (loader role)
    const int w   = tid & 31;

    // ldmatrix lane address components
    const int g  = lane >> 3, rl = lane & 7;
    const int aRowLane = ((g & 1) << 3) + rl;
    const int aKLane   = (g >> 1) << 4;
    const int bRowLane = ((g >> 1) << 3) + rl;
    const int bKLane   = (g & 1) << 4;

    const float2* x2 = (const float2*)x;

    for (int tile = blockIdx.x; tile < NUM_TILES; tile += GRID) {
        const int mt_id = tile >> 1;
        const int nh    = tile & 1;           // n-half: [nh*96, nh*96+96)
        const int m0 = mt_id * 128;
        const int b  = m0 >> 14;
        const int d  = (m0 >> 10) & 15;
        const int h0 = (m0 >> 5) & 31;
        const size_t baseIdx = ((size_t)(b * 96 + idx) * 32 + 2 * d) * 2048 + (size_t)(2 * h0) * 32 + w;

        __syncthreads();   // previous tile's epilogue fully done (sbuf overlaps A/B)

        float acc[2][6][4];
#pragma unroll
        for (int mt = 0; mt < 2; mt++)
#pragma unroll
            for (int ng = 0; ng < 6; ng++)
#pragma unroll
                for (int r = 0; r < 4; r++) acc[mt][ng][r] = 0.f;

        float sA[4] = {0.f, 0.f, 0.f, 0.f};
        float sQ[4] = {0.f, 0.f, 0.f, 0.f};
        uint32_t aPk[16];

        // ---- prologue: stream B(0) half; load+convert A chunk 0 ----
        {
            const float4* bsrc = g_Bh + nh * 768 + tid;
#pragma unroll
            for (int j = 0; j < 3; j++)
                cpa16(sb + SMEM_B0 + (uint32_t)(j * 256 + tid) * 16, bsrc + j * 256);
            CP_COMMIT();
        }
#pragma unroll
        for (int i = 0; i < 16; i++) {
            float2 v = x2[baseIdx + (size_t)((i >> 3) * 2048 + ((i >> 1) & 3) * 64 + (i & 1) * 32)];
            const int hout = (i >> 1) & 3;
            sA[hout] += v.x + v.y;
            sQ[hout] = fmaf(v.x, v.x, fmaf(v.y, v.y, sQ[hout]));
            __half2 h2 = __float22half2_rn(v);
            aPk[i] = *(uint32_t*)&h2;
        }

        for (int t = 0; t < 12; t++) {
            // ---- STS A(t): 4x STS.128 ----
            unsigned char* abase = smem + (t & 1 ? SMEM_A1 : SMEM_A0);
#pragma unroll
            for (int hout = 0; hout < 4; hout++) {
                uint4 pk;
                pk.x = aPk[hout * 2];
                pk.y = aPk[hout * 2 + 1];
                pk.z = aPk[hout * 2 + 8];
                pk.w = aPk[hout * 2 + 9];
                uint32_t off = swz128((uint32_t)((hout * 32 + w) * 128 + idx * 16));
                *(uint4*)(abase + off) = pk;
            }
            CP_WAIT0();            // B(t) staged
            __syncthreads();

            // ---- stream B(t+1) half; load+convert A(t+1) ----
            if (t < 11) {
                const float4* bsrc = g_Bh + (size_t)(t + 1) * 1536 + nh * 768 + tid;
                uint32_t bdst = sb + ((t + 1) & 1 ? SMEM_B1 : SMEM_B0);
#pragma unroll
                for (int j = 0; j < 3; j++)
                    cpa16(bdst + (uint32_t)(j * 256 + tid) * 16, bsrc + j * 256);
                CP_COMMIT();
                const size_t cb = baseIdx + (size_t)(t + 1) * 524288;
#pragma unroll
                for (int i = 0; i < 16; i++) {
                    float2 v = x2[cb + (size_t)((i >> 3) * 2048 + ((i >> 1) & 3) * 64 + (i & 1) * 32)];
                    const int hout = (i >> 1) & 3;
                    sA[hout] += v.x + v.y;
                    sQ[hout] = fmaf(v.x, v.x, fmaf(v.y, v.y, sQ[hout]));
                    __half2 h2 = __float22half2_rn(v);
                    aPk[i] = *(uint32_t*)&h2;
                }
            }

            // ---- compute: 4 k16-steps ----
            const uint32_t abuf  = sb + (t & 1 ? SMEM_A1 : SMEM_A0);
            const uint32_t bbase = sb + (t & 1 ? SMEM_B1 : SMEM_B0);
#pragma unroll
            for (int ks = 0; ks < 4; ks++) {
                uint32_t ahi[2][4];
#pragma unroll
                for (int mt = 0; mt < 2; mt++) {
                    uint32_t rowoff = (uint32_t)((wm * 32 + mt * 16 + aRowLane) * 128 + ks * 32 + aKLane);
                    ldsm4(ahi[mt], abuf + swz128(rowoff));
                }
#pragma unroll
                for (int ng2 = 0; ng2 < 3; ng2++) {
                    uint32_t boff = (uint32_t)((wn * 48 + ng2 * 16 + bRowLane) * 128 + ks * 32 + bKLane);
                    uint32_t bb[4];
                    ldsm4(bb, bbase + swz128(boff));
                    mma16816(acc[0][2 * ng2],     ahi[0], bb[0], bb[1]);
                    mma16816(acc[1][2 * ng2],     ahi[1], bb[0], bb[1]);
                    mma16816(acc[0][2 * ng2 + 1], ahi[0], bb[2], bb[3]);
                    mma16816(acc[1][2 * ng2 + 1], ahi[1], bb[2], bb[3]);
                }
            }
        }
        __syncthreads();

        // ---- LayerNorm stats reduce ----
        float* psum = (float*)(smem + OFF_PSUM);
        float* psq  = (float*)(smem + OFF_PSQ);
#pragma unroll
        for (int hout = 0; hout < 4; hout++) {
            psum[idx * 128 + hout * 32 + w] = sA[hout];
            psq[idx * 128 + hout * 32 + w]  = sQ[hout];
        }
        __syncthreads();
        float* stat = (float*)(smem + OFF_STAT);
        if (tid < 128) {
            float S = 0.f, Q = 0.f;
#pragma unroll
            for (int r = 0; r < 8; r++) { S += psum[r * 128 + tid]; Q += psq[r * 128 + tid]; }
            float mu  = S * (1.0f / 768.0f);
            float var = Q * (1.0f / 768.0f) - mu * mu;
            float rs  = rsqrtf(var + 1e-5f);
            stat[tid]       = rs;
            stat[128 + tid] = -rs * mu;
        }
        __syncthreads();

        // ---- epilogue: LN affine + transposed writeback (96 n, single pass) ----
        float* sbuf = (float*)smem;   // 96 x 128 floats = 48 KB (overlaps tiles)
        const int sp0 = (m0 & 16383);
#pragma unroll
        for (int mt = 0; mt < 2; mt++)
#pragma unroll
            for (int ng = 0; ng < 6; ng++)
#pragma unroll
                for (int r = 0; r < 4; r++) {
                    int m_loc = wm * 32 + mt * 16 + (lane >> 2) + ((r >> 1) << 3);
                    int n_loc = wn * 48 + ng * 8 + ((lane & 3) << 1) + (r & 1);
                    int n_glb = nh * 96 + n_loc;
                    float v = fmaf(stat[m_loc], acc[mt][ng][r],
                                   fmaf(stat[128 + m_loc], __ldg(&g_s1[n_glb]), __ldg(&g_s2[n_glb])));
                    sbuf[n_loc * 128 + m_loc] = v;
                }
        __syncthreads();
#pragma unroll
        for (int r = 0; r < 48; r++) {
            int e  = r * 256 + tid;
            int nl = e >> 7;
            int ml = e & 127;
            int n  = nh * 96 + nl;
            out[(size_t)(b * 192 + n) * 16384 + sp0 + ml] = sbuf[e];
        }
    }
}

// ---------------- launch ----------------
extern "C" void kernel_launch(void* const* d_in, const int* in_sizes, int n_in,
                              void* d_out, int out_size) {
    const float* x     = (const float*)d_in[0];
    const float* gamma = (const float*)d_in[1];
    const float* beta  = (const float*)d_in[2];
    const float* w_red = (const float*)d_in[3];
    float* out = (float*)d_out;

    cudaFuncSetAttribute(k_main, cudaFuncAttributeMaxDynamicSharedMemorySize, SMEM_TOTAL);

    k_prep<<<768, 256>>>(gamma, beta, w_red);
    k_main<<<GRID, 256, SMEM_TOTAL>>>(x, out);
}

// round 17
// speedup vs baseline: 1.2842x; 1.2842x over previous
#include <cuda_runtime.h>
#include <cuda_fp16.h>
#include <cstdint>

// ============================================================================
// helpers
// ============================================================================
__device__ __forceinline__ uint32_t smem_u32(const void* p) {
    uint32_t a;
    asm("{ .reg .u64 t; cvta.to.shared.u64 t, %1; cvt.u32.u64 %0, t; }" : "=r"(a) : "l"(p));
    return a;
}
__host__ __device__ __forceinline__ uint32_t swz128(uint32_t off) {
    return off ^ ((off >> 3) & 0x70);
}
__device__ __forceinline__ void ldsm4(uint32_t r[4], uint32_t addr) {
    asm volatile("ldmatrix.sync.aligned.m8n8.x4.shared.b16 {%0,%1,%2,%3}, [%4];"
                 : "=r"(r[0]), "=r"(r[1]), "=r"(r[2]), "=r"(r[3]) : "r"(addr));
}
__device__ __forceinline__ void mma16816(float d[4], const uint32_t a[4], uint32_t b0, uint32_t b1) {
    asm volatile("mma.sync.aligned.m16n8k16.row.col.f32.f16.f16.f32 "
                 "{%0,%1,%2,%3}, {%4,%5,%6,%7}, {%8,%9}, {%0,%1,%2,%3};"
                 : "+f"(d[0]), "+f"(d[1]), "+f"(d[2]), "+f"(d[3])
                 : "r"(a[0]), "r"(a[1]), "r"(a[2]), "r"(a[3]), "r"(b0), "r"(b1));
}
__device__ __forceinline__ void cpa16(uint32_t dst, const void* src) {
    asm volatile("cp.async.cg.shared.global [%0], [%1], 16;" :: "r"(dst), "l"(src));
}
#define CP_COMMIT() asm volatile("cp.async.commit_group;" ::: "memory")
#define CP_WAIT0()  asm volatile("cp.async.wait_group 0;" ::: "memory")

// ============================================================================
// smem layout (per CTA 82,944 B; 2 CTAs/SM)
// ============================================================================
static constexpr int SMEM_A0   = 0;        // 16 KB: A 128x64 fp16, SW128 rows (buf 0)
static constexpr int SMEM_A1   = 16384;    // 16 KB: A buf 1
static constexpr int SMEM_B0   = 32768;    // 24 KB: B buffer 0
static constexpr int SMEM_B1   = 57344;    // 24 KB: B buffer 1
static constexpr int OFF_PSUM  = 32768;    // reuse B0 after compute
static constexpr int OFF_PSQ   = 36864;
static constexpr int OFF_STAT  = 81920;    // 1 KB
static constexpr int SMEM_TOTAL = 82944;

// ---------------- device scratch ----------------
__device__ float  g_s1[192];
__device__ float  g_s2[192];
__device__ float4 g_Bh[12 * 1536];   // 12 chunks x 24KB, pre-swizzled tile layout (fp16)

// ---------------- prep kernel: B plane + s1/s2 ----------------
__global__ void k_prep(const float* __restrict__ gamma, const float* __restrict__ beta,
                       const float* __restrict__ w) {
    if (blockIdx.x < 576) {
        int t = blockIdx.x * 256 + threadIdx.x;
        int k = t / 192;       // original k = p*96 + c
        int n = t % 192;
        int p = k / 96, c = k % 96;
        float val = gamma[k] * w[k * 192 + n];
        int chunk = c >> 3;
        int kl = (c & 7) * 8 + p;              // k-hat within chunk
        uint32_t off = swz128((uint32_t)(n * 128 + kl * 2));
        *(__half*)((unsigned char*)g_Bh + chunk * 24576 + off) = __float2half_rn(val);
    } else {
        int n = blockIdx.x - 576;
        __shared__ float s1s[256], s2s[256];
        float s1 = 0.f, s2 = 0.f;
        for (int k = threadIdx.x; k < 768; k += 256) {
            float wv = w[k * 192 + n];
            s1 += gamma[k] * wv;
            s2 += beta[k] * wv;
        }
        s1s[threadIdx.x] = s1; s2s[threadIdx.x] = s2;
        __syncthreads();
        for (int off = 128; off > 0; off >>= 1) {
            if (threadIdx.x < off) { s1s[threadIdx.x] += s1s[threadIdx.x + off]; s2s[threadIdx.x] += s2s[threadIdx.x + off]; }
            __syncthreads();
        }
        if (threadIdx.x == 0) { g_s1[n] = s1s[0]; g_s2[n] = s2s[0]; }
    }
}

// ---------------- main fused kernel ----------------
__global__ void __launch_bounds__(256, 2) k_main(const float* __restrict__ x,
                                                 float* __restrict__ out) {
    extern __shared__ unsigned char smem[];
    const uint32_t sb  = smem_u32(smem);
    const int tid  = threadIdx.x;
    const int lane = tid & 31;
    const int wrp  = tid >> 5;
    const int wm   = wrp & 3;       // M quadrant (32 rows)
    const int wn   = wrp >> 2;      // N half (96 cols)

    // block coords: 128 consecutive m
    const int m0 = blockIdx.x * 128;
    const int b  = m0 >> 14;
    const int d  = (m0 >> 10) & 15;
    const int h0 = (m0 >> 5) & 31;     // multiple of 4
    const int idx = tid >> 5;          // c_local 0..7 (loader role)
    const int w   = tid & 31;

    const float2* x2 = (const float2*)x;
    const size_t baseIdx = ((size_t)(b * 96 + idx) * 32 + 2 * d) * 2048 + (size_t)(2 * h0) * 32 + w;

    // ldmatrix lane address components
    const int g  = lane >> 3, rl = lane & 7;
    const int aRowLane = ((g & 1) << 3) + rl;
    const int aKLane   = (g >> 1) << 4;
    const int bRowLane = ((g >> 1) << 3) + rl;
    const int bKLane   = (g & 1) << 4;

    float acc[2][12][4];
#pragma unroll
    for (int mt = 0; mt < 2; mt++)
#pragma unroll
        for (int ng = 0; ng < 12; ng++)
#pragma unroll
            for (int r = 0; r < 4; r++) acc[mt][ng][r] = 0.f;

    float sA[4] = {0.f, 0.f, 0.f, 0.f};
    float sQ[4] = {0.f, 0.f, 0.f, 0.f};

    // ---- prologue: stream B(0); load+convert+STS A chunk 0 into A0 ----
    {
        const float4* bsrc = g_Bh + tid;
#pragma unroll
        for (int j = 0; j < 6; j++)
            cpa16(sb + SMEM_B0 + (uint32_t)(j * 256 + tid) * 16, bsrc + j * 256);
        CP_COMMIT();
    }
#pragma unroll
    for (int half = 0; half < 2; half++) {
        float2 raw[8];
#pragma unroll
        for (int j = 0; j < 8; j++) {
            const int dz = j >> 2, hh = (j >> 1) & 1, hy = j & 1;
            raw[j] = x2[baseIdx + (size_t)(dz * 2048 + (half * 2 + hh) * 64 + hy * 32)];
        }
#pragma unroll
        for (int hh = 0; hh < 2; hh++) {
            const int hout = half * 2 + hh;
            float2 v00 = raw[hh * 2], v01 = raw[hh * 2 + 1], v10 = raw[4 + hh * 2], v11 = raw[4 + hh * 2 + 1];
            sA[hout] += (v00.x + v00.y) + (v01.x + v01.y) + (v10.x + v10.y) + (v11.x + v11.y);
            float q = fmaf(v00.x, v00.x, v00.y * v00.y);
            q = fmaf(v01.x, v01.x, fmaf(v01.y, v01.y, q));
            q = fmaf(v10.x, v10.x, fmaf(v10.y, v10.y, q));
            q = fmaf(v11.x, v11.x, fmaf(v11.y, v11.y, q));
            sQ[hout] += q;
            uint4 pk;
            __half2 h00 = __float22half2_rn(v00); pk.x = *(uint32_t*)&h00;
            __half2 h01 = __float22half2_rn(v01); pk.y = *(uint32_t*)&h01;
            __half2 h10 = __float22half2_rn(v10); pk.z = *(uint32_t*)&h10;
            __half2 h11 = __float22half2_rn(v11); pk.w = *(uint32_t*)&h11;
            *(uint4*)(smem + SMEM_A0 + swz128((uint32_t)((hout * 32 + w) * 128 + idx * 16))) = pk;
        }
    }

    for (int t = 0; t < 12; t++) {
        const uint32_t abuf  = sb + (t & 1 ? SMEM_A1 : SMEM_A0);
        const uint32_t bbase = sb + (t & 1 ? SMEM_B1 : SMEM_B0);
        unsigned char* anext = smem + ((t + 1) & 1 ? SMEM_A1 : SMEM_A0);

        CP_WAIT0();            // B(t) staged
        __syncthreads();       // STS(t) visible; compute(t-1) done everywhere

        const bool more = (t < 11);
        size_t cb = 0;
        float2 raw[8];
        if (more) {
            // issue B(t+1)
            const float4* bsrc = g_Bh + (size_t)(t + 1) * 1536 + tid;
            uint32_t bdst = sb + ((t + 1) & 1 ? SMEM_B1 : SMEM_B0);
#pragma unroll
            for (int j = 0; j < 6; j++)
                cpa16(bdst + (uint32_t)(j * 256 + tid) * 16, bsrc + j * 256);
            CP_COMMIT();
            // issue LDG raw half1 (hout 0,1) of A(t+1)
            cb = baseIdx + (size_t)(t + 1) * 524288;
#pragma unroll
            for (int j = 0; j < 8; j++) {
                const int dz = j >> 2, hh = (j >> 1) & 1, hy = j & 1;
                raw[j] = x2[cb + (size_t)(dz * 2048 + hh * 64 + hy * 32)];
            }
        }

        // ---- compute ks 0,1 (LDGs land underneath) ----
#pragma unroll
        for (int ks = 0; ks < 2; ks++) {
            uint32_t ahi[2][4];
#pragma unroll
            for (int mt = 0; mt < 2; mt++) {
                uint32_t rowoff = (uint32_t)((wm * 32 + mt * 16 + aRowLane) * 128 + ks * 32 + aKLane);
                ldsm4(ahi[mt], abuf + swz128(rowoff));
            }
#pragma unroll
            for (int ng2 = 0; ng2 < 6; ng2++) {
                uint32_t boff = (uint32_t)((wn * 96 + ng2 * 16 + bRowLane) * 128 + ks * 32 + bKLane);
                uint32_t bb[4];
                ldsm4(bb, bbase + swz128(boff));
                mma16816(acc[0][2 * ng2],     ahi[0], bb[0], bb[1]);
                mma16816(acc[1][2 * ng2],     ahi[1], bb[0], bb[1]);
                mma16816(acc[0][2 * ng2 + 1], ahi[0], bb[2], bb[3]);
                mma16816(acc[1][2 * ng2 + 1], ahi[1], bb[2], bb[3]);
            }
        }

        if (more) {
            // cvt+stats+STS half1 (hout 0,1); then issue LDG half2 (hout 2,3)
#pragma unroll
            for (int hh = 0; hh < 2; hh++) {
                const int hout = hh;
                float2 v00 = raw[hh * 2], v01 = raw[hh * 2 + 1], v10 = raw[4 + hh * 2], v11 = raw[4 + hh * 2 + 1];
                sA[hout] += (v00.x + v00.y) + (v01.x + v01.y) + (v10.x + v10.y) + (v11.x + v11.y);
                float q = fmaf(v00.x, v00.x, v00.y * v00.y);
                q = fmaf(v01.x, v01.x, fmaf(v01.y, v01.y, q));
                q = fmaf(v10.x, v10.x, fmaf(v10.y, v10.y, q));
                q = fmaf(v11.x, v11.x, fmaf(v11.y, v11.y, q));
                sQ[hout] += q;
                uint4 pk;
                __half2 h00 = __float22half2_rn(v00); pk.x = *(uint32_t*)&h00;
                __half2 h01 = __float22half2_rn(v01); pk.y = *(uint32_t*)&h01;
                __half2 h10 = __float22half2_rn(v10); pk.z = *(uint32_t*)&h10;
                __half2 h11 = __float22half2_rn(v11); pk.w = *(uint32_t*)&h11;
                *(uint4*)(anext + swz128((uint32_t)((hout * 32 + w) * 128 + idx * 16))) = pk;
            }
#pragma unroll
            for (int j = 0; j < 8; j++) {
                const int dz = j >> 2, hh = (j >> 1) & 1, hy = j & 1;
                raw[j] = x2[cb + (size_t)(dz * 2048 + (2 + hh) * 64 + hy * 32)];
            }
        }

        // ---- compute ks 2,3 ----
#pragma unroll
        for (int ks = 2; ks < 4; ks++) {
            uint32_t ahi[2][4];
#pragma unroll
            for (int mt = 0; mt < 2; mt++) {
                uint32_t rowoff = (uint32_t)((wm * 32 + mt * 16 + aRowLane) * 128 + ks * 32 + aKLane);
                ldsm4(ahi[mt], abuf + swz128(rowoff));
            }
#pragma unroll
            for (int ng2 = 0; ng2 < 6; ng2++) {
                uint32_t boff = (uint32_t)((wn * 96 + ng2 * 16 + bRowLane) * 128 + ks * 32 + bKLane);
                uint32_t bb[4];
                ldsm4(bb, bbase + swz128(boff));
                mma16816(acc[0][2 * ng2],     ahi[0], bb[0], bb[1]);
                mma16816(acc[1][2 * ng2],     ahi[1], bb[0], bb[1]);
                mma16816(acc[0][2 * ng2 + 1], ahi[0], bb[2], bb[3]);
                mma16816(acc[1][2 * ng2 + 1], ahi[1], bb[2], bb[3]);
            }
        }

        if (more) {
            // cvt+stats+STS half2 (hout 2,3)
#pragma unroll
            for (int hh = 0; hh < 2; hh++) {
                const int hout = 2 + hh;
                float2 v00 = raw[hh * 2], v01 = raw[hh * 2 + 1], v10 = raw[4 + hh * 2], v11 = raw[4 + hh * 2 + 1];
                sA[hout] += (v00.x + v00.y) + (v01.x + v01.y) + (v10.x + v10.y) + (v11.x + v11.y);
                float q = fmaf(v00.x, v00.x, v00.y * v00.y);
                q = fmaf(v01.x, v01.x, fmaf(v01.y, v01.y, q));
                q = fmaf(v10.x, v10.x, fmaf(v10.y, v10.y, q));
                q = fmaf(v11.x, v11.x, fmaf(v11.y, v11.y, q));
                sQ[hout] += q;
                uint4 pk;
                __half2 h00 = __float22half2_rn(v00); pk.x = *(uint32_t*)&h00;
                __half2 h01 = __float22half2_rn(v01); pk.y = *(uint32_t*)&h01;
                __half2 h10 = __float22half2_rn(v10); pk.z = *(uint32_t*)&h10;
                __half2 h11 = __float22half2_rn(v11); pk.w = *(uint32_t*)&h11;
                *(uint4*)(anext + swz128((uint32_t)((hout * 32 + w) * 128 + idx * 16))) = pk;
            }
        }
    }
    __syncthreads();

    // ---- LayerNorm stats reduce ----
    float* psum = (float*)(smem + OFF_PSUM);
    float* psq  = (float*)(smem + OFF_PSQ);
#pragma unroll
    for (int hout = 0; hout < 4; hout++) {
        psum[idx * 128 + hout * 32 + w] = sA[hout];
        psq[idx * 128 + hout * 32 + w]  = sQ[hout];
    }
    __syncthreads();
    float* stat = (float*)(smem + OFF_STAT);
    if (tid < 128) {
        float S = 0.f, Q = 0.f;
#pragma unroll
        for (int r = 0; r < 8; r++) { S += psum[r * 128 + tid]; Q += psq[r * 128 + tid]; }
        float mu  = S * (1.0f / 768.0f);
        float var = Q * (1.0f / 768.0f) - mu * mu;
        float rs  = rsqrtf(var + 1e-5f);
        stat[tid]       = rs;
        stat[128 + tid] = -rs * mu;
    }
    __syncthreads();

    // ---- epilogue: LN affine + transposed writeback (two n-halves of 96) ----
    float* sbuf = (float*)smem;   // 96 x 128 floats = 48 KB (overlaps tiles)
    const int sp0 = (m0 & 16383);
    for (int h = 0; h < 2; h++) {
        if (wn == h) {
#pragma unroll
            for (int mt = 0; mt < 2; mt++)
#pragma unroll
                for (int ng = 0; ng < 12; ng++)
#pragma unroll
                    for (int r = 0; r < 4; r++) {
                        int m_loc = wm * 32 + mt * 16 + (lane >> 2) + ((r >> 1) << 3);
                        int n_loc = ng * 8 + ((lane & 3) << 1) + (r & 1);
                        int n_glb = h * 96 + n_loc;
                        float v = fmaf(stat[m_loc], acc[mt][ng][r],
                                       fmaf(stat[128 + m_loc], __ldg(&g_s1[n_glb]), __ldg(&g_s2[n_glb])));
                        sbuf[n_loc * 128 + m_loc] = v;
                    }
        }
        __syncthreads();
#pragma unroll
        for (int r = 0; r < 48; r++) {
            int e  = r * 256 + tid;
            int nl = e >> 7;
            int ml = e & 127;
            int n  = h * 96 + nl;
            out[(size_t)(b * 192 + n) * 16384 + sp0 + ml] = sbuf[e];
        }
        if (h == 0) __syncthreads();
    }
}

// ---------------- launch ----------------
extern "C" void kernel_launch(void* const* d_in, const int* in_sizes, int n_in,
                              void* d_out, int out_size) {
    const float* x     = (const float*)d_in[0];
    const float* gamma = (const float*)d_in[1];
    const float* beta  = (const float*)d_in[2];
    const float* w_red = (const float*)d_in[3];
    float* out = (float*)d_out;

    cudaFuncSetAttribute(k_main, cudaFuncAttributeMaxDynamicSharedMemorySize, SMEM_TOTAL);

    k_prep<<<768, 256>>>(gamma, beta, w_red);
    k_main<<<256, 256, SMEM_TOTAL>>>(x, out);
}